// round 14
// baseline (speedup 1.0000x reference)
#include <cuda_runtime.h>
#include <cuda_bf16.h>
#include <cstdint>
#include <cstddef>

#define CN 22
#define FN 192
#define HN 128
#define TM 88                   // CTA M-tile = 4 bt-groups
#define G  4
#define NTH 384                 // 12 warps: 6 M x 2 N for GEMMs

// weights pre-split bf16 hi/lo, MMA-fragment order: t = s*512 + f*32 + lane
__device__ uint4 g_W0s[(FN / 16) * 512];
__device__ uint4 g_W1s[(HN / 16) * 512];

// ---- smem layout (bytes) ----
#define USTRIDE 132
#define OFF_U   0               // float sU[88][132] = 46464 (X bufs alias inside)
#define XSTRIDE 20              // uint2 per row
#define XBUF    15360           // 96 rows * 160B
#define OFF_H   46464           // uint2 sH[96][68] = 52224  (sP aliases here later)
#define HSTRIDE 68
#define OFF_AS  98688           // uint2 sAs[4][32][17] = 17408
#define ASTRIDE 17
#define SMEM_TOTAL 116096       // 113.4 KB -> 2 CTAs/SM

__device__ __forceinline__ uint32_t pack_bf16(float x, float y) {
    __nv_bfloat162 p;
    p.x = __float2bfloat16(x);
    p.y = __float2bfloat16(y);
    return *reinterpret_cast<uint32_t*>(&p);
}
__device__ __forceinline__ uint32_t pack_bf16_resid(float x, float y, uint32_t hi) {
    __nv_bfloat162 h = *reinterpret_cast<__nv_bfloat162*>(&hi);
    return pack_bf16(x - __bfloat162float(h.x), y - __bfloat162float(h.y));
}

// ---- weight prep: W [128][K] fp32 -> fragment-order split bf16 ----
__global__ void prep_w(const float* __restrict__ W, int K, uint4* __restrict__ out) {
    int t = blockIdx.x * blockDim.x + threadIdx.x;
    int total = (K / 16) * 512;
    if (t >= total) return;
    int l = t & 31;
    int f = (t >> 5) & 15;
    int s = t >> 9;
    int n = f * 8 + (l >> 2);
    int k0 = s * 16 + (l & 3) * 2;
    const float* wr = W + (size_t)n * K;
    float w00 = wr[k0], w01 = wr[k0 + 1], w10 = wr[k0 + 8], w11 = wr[k0 + 9];
    uint32_t h0 = pack_bf16(w00, w01), h1 = pack_bf16(w10, w11);
    uint32_t l0 = pack_bf16_resid(w00, w01, h0), l1 = pack_bf16_resid(w10, w11, h1);
    out[t] = make_uint4(h0, h1, l0, l1);
}

// ---- mma.sync m16n8k16 row.col bf16 -> f32 ----
__device__ __forceinline__ void mma_bf16(float* c, const uint32_t* a, uint32_t b0, uint32_t b1) {
    asm volatile(
        "mma.sync.aligned.m16n8k16.row.col.f32.bf16.bf16.f32 "
        "{%0,%1,%2,%3}, {%4,%5,%6,%7}, {%8,%9}, {%0,%1,%2,%3};"
        : "+f"(c[0]), "+f"(c[1]), "+f"(c[2]), "+f"(c[3])
        : "r"(a[0]), "r"(a[1]), "r"(a[2]), "r"(a[3]), "r"(b0), "r"(b1));
}

// stage 8 fp32 (one thread's k-quarter) as interleaved {hi,lo} uint2 pairs
__device__ __forceinline__ void stage_x(char* buf, int sr, int sq, float4 a, float4 b) {
    uint32_t h0 = pack_bf16(a.x, a.y), h1 = pack_bf16(a.z, a.w);
    uint32_t h2 = pack_bf16(b.x, b.y), h3 = pack_bf16(b.z, b.w);
    uint32_t l0 = pack_bf16_resid(a.x, a.y, h0), l1 = pack_bf16_resid(a.z, a.w, h1);
    uint32_t l2 = pack_bf16_resid(b.x, b.y, h2), l3 = pack_bf16_resid(b.z, b.w, h3);
    uint4* dst = reinterpret_cast<uint4*>(buf + (size_t)sr * (XSTRIDE * 8) + sq * 32);
    dst[0] = make_uint4(h0, l0, h1, l1);
    dst[1] = make_uint4(h2, l2, h3, l3);
}

// ---- tensor-core A-mix for one unit = (gg, m-tile, n-half) ----
// D[c,h] = sum_j A[c,j]*U[j,h]; 3-term bf16 split both sides.
// MEAN=false: relu+bias -> split-pack -> sH (layer-2 a-frag layout)
// MEAN=true : relu+bias -> column sums (shuffle-reduce over c) -> sP
template <bool MEAN>
__device__ __forceinline__ void mix_mma(
    int unit, int g, int q, int l,
    const float* __restrict__ sU, const uint2* __restrict__ sAs,
    uint2* __restrict__ sH, float* __restrict__ sP,
    const float* __restrict__ bias)
{
    const int gg = unit >> 2, mt = (unit >> 1) & 1, nh = unit & 1;
    float mac[8][4];
#pragma unroll
    for (int f = 0; f < 8; f++)
#pragma unroll
        for (int i = 0; i < 4; i++) mac[f][i] = 0.f;

    const uint2* aRow  = sAs + (gg * 32 + mt * 16 + g) * ASTRIDE;
    const uint2* aRow8 = aRow + 8 * ASTRIDE;
    const float* uBase = sU + (gg * CN) * USTRIDE;

#pragma unroll
    for (int sp = 0; sp < 2; sp++) {
        uint2 a0 = aRow [sp * 8 + q];
        uint2 a1 = aRow8[sp * 8 + q];
        uint2 a2 = aRow [sp * 8 + q + 4];
        uint2 a3 = aRow8[sp * 8 + q + 4];
        uint32_t ah[4] = { a0.x, a1.x, a2.x, a3.x };
        uint32_t al[4] = { a0.y, a1.y, a2.y, a3.y };
        const int j0 = sp * 16 + 2 * q;
        const bool v0 = (sp == 0) || (q < 3);   // j0, j0+1 valid?
        const bool v1 = (sp == 0);              // j0+8, j0+9 valid?
#pragma unroll
        for (int f = 0; f < 8; f++) {
            const int hc = nh * 64 + f * 8 + g;   // B-frag n = lane>>2
            float u0a = v0 ? uBase[(j0)     * USTRIDE + hc] : 0.f;
            float u0b = v0 ? uBase[(j0 + 1) * USTRIDE + hc] : 0.f;
            float u1a = v1 ? uBase[(j0 + 8) * USTRIDE + hc] : 0.f;
            float u1b = v1 ? uBase[(j0 + 9) * USTRIDE + hc] : 0.f;
            uint32_t bh0 = pack_bf16(u0a, u0b), bh1 = pack_bf16(u1a, u1b);
            uint32_t bl0 = pack_bf16_resid(u0a, u0b, bh0);
            uint32_t bl1 = pack_bf16_resid(u1a, u1b, bh1);
            mma_bf16(mac[f], ah, bh0, bh1);
            mma_bf16(mac[f], al, bh0, bh1);
            mma_bf16(mac[f], ah, bl0, bl1);
        }
    }

    const int c  = mt * 16 + g;      // rows for mac[f][0..1]
    const int c8 = c + 8;            // rows for mac[f][2..3]
#pragma unroll
    for (int f = 0; f < 8; f++) {
        const int hc = nh * 64 + f * 8 + 2 * q;   // D-frag cols = 2q, 2q+1
        float2 bb = __ldg(reinterpret_cast<const float2*>(bias + hc));
        if (!MEAN) {
            if (c < CN) {
                float w0 = fmaxf(mac[f][0] + bb.x, 0.f);
                float w1 = fmaxf(mac[f][1] + bb.y, 0.f);
                uint32_t hi = pack_bf16(w0, w1);
                sH[(gg * CN + c) * HSTRIDE + (hc >> 1)] =
                    make_uint2(hi, pack_bf16_resid(w0, w1, hi));
            }
            if (c8 < CN) {
                float w2 = fmaxf(mac[f][2] + bb.x, 0.f);
                float w3 = fmaxf(mac[f][3] + bb.y, 0.f);
                uint32_t hi = pack_bf16(w2, w3);
                sH[(gg * CN + c8) * HSTRIDE + (hc >> 1)] =
                    make_uint2(hi, pack_bf16_resid(w2, w3, hi));
            }
        } else {
            float t0 = 0.f, t1 = 0.f;
            if (c < CN) {
                t0 += fmaxf(mac[f][0] + bb.x, 0.f);
                t1 += fmaxf(mac[f][1] + bb.y, 0.f);
            }
            if (c8 < CN) {
                t0 += fmaxf(mac[f][2] + bb.x, 0.f);
                t1 += fmaxf(mac[f][3] + bb.y, 0.f);
            }
#pragma unroll
            for (int d = 4; d <= 16; d <<= 1) {
                t0 += __shfl_xor_sync(0xFFFFFFFFu, t0, d);
                t1 += __shfl_xor_sync(0xFFFFFFFFu, t1, d);
            }
            if (l < 4) {
                float* p = sP + (gg * 2 + mt) * HN + hc;
                p[0] = t0;
                p[1] = t1;
            }
        }
    }
}

// ---- whole network, one kernel ----
__global__ void __launch_bounds__(NTH, 2) fused_all(
    const float* __restrict__ x,
    const uint4* __restrict__ W0s, const uint4* __restrict__ W1s,
    const float* __restrict__ A,
    const float* __restrict__ b0, const float* __restrict__ b1,
    float* __restrict__ out)
{
    extern __shared__ __align__(16) char sm[];
    const int t = threadIdx.x;
    const int wid = t >> 5, l = t & 31;
    const int g = l >> 2, q = l & 3;
    const int wm = wid >> 1, wn = wid & 1;
    const int rb = wm * 16;
    const int row0 = blockIdx.x * TM;
    const int bt0 = blockIdx.x * G;

    float* sU  = reinterpret_cast<float*>(sm + OFF_U);
    uint2* sH  = reinterpret_cast<uint2*>(sm + OFF_H);
    float* sP  = reinterpret_cast<float*>(sm + OFF_H);   // alias (sH dead by mix2)
    uint2* sAs = reinterpret_cast<uint2*>(sm + OFF_AS);

    // ---- build split adjacency fragments (zeros pad c>=22, j>=22) ----
    {
        const float* Ag = A + (size_t)bt0 * (CN * CN);
        for (int i = t; i < G * 32 * 16; i += NTH) {
            int jp = i & 15;
            int c  = (i >> 4) & 31;
            int gg = i >> 9;
            float2 v = make_float2(0.f, 0.f);
            if (c < CN && jp < 11)
                v = *reinterpret_cast<const float2*>(Ag + gg * (CN * CN) + c * CN + 2 * jp);
            uint32_t hi = pack_bf16(v.x, v.y);
            sAs[(gg * 32 + c) * ASTRIDE + jp] =
                make_uint2(hi, pack_bf16_resid(v.x, v.y, hi));
        }
    }

    float acc[8][4];
#pragma unroll
    for (int f = 0; f < 8; f++)
#pragma unroll
        for (int i = 0; i < 4; i++) acc[f][i] = 0.f;

    // ---- phase 1: U = x @ W0^T (K=192) ----
    const int sr = t >> 2, sq = t & 3;
    const bool stager = (t < TM * 4);
    const float* xrow = x + (size_t)(row0 + sr) * FN + sq * 8;

    if (stager) {
        float4 a0 = *reinterpret_cast<const float4*>(xrow);
        float4 a1 = *reinterpret_cast<const float4*>(xrow + 4);
        stage_x(sm, sr, sq, a0, a1);
    }
    __syncthreads();

    constexpr int NC1 = FN / 32;   // 6
#pragma unroll 1
    for (int kc = 0; kc < NC1; kc++) {
        char* bufc = sm + (kc & 1) * XBUF;
        char* bufn = sm + ((kc & 1) ^ 1) * XBUF;
        float4 xv0, xv1;
        const bool pf = stager && (kc + 1 < NC1);
        if (pf) {
            xv0 = *reinterpret_cast<const float4*>(xrow + (kc + 1) * 32);
            xv1 = *reinterpret_cast<const float4*>(xrow + (kc + 1) * 32 + 4);
        }
        const uint2* sX = reinterpret_cast<const uint2*>(bufc);
#pragma unroll
        for (int sp = 0; sp < 2; sp++) {
            int p0 = sp * 8 + q;
            uint2 u00 = sX[(rb + g) * XSTRIDE + p0];
            uint2 u10 = sX[(rb + 8 + g) * XSTRIDE + p0];
            uint2 u01 = sX[(rb + g) * XSTRIDE + p0 + 4];
            uint2 u11 = sX[(rb + 8 + g) * XSTRIDE + p0 + 4];
            uint32_t ah[4] = { u00.x, u10.x, u01.x, u11.x };
            uint32_t al[4] = { u00.y, u10.y, u01.y, u11.y };
            const uint4* Wp = W0s + (size_t)(kc * 2 + sp) * 512 + wn * 256 + l;
#pragma unroll
            for (int f = 0; f < 8; f++) {
                uint4 bv = __ldg(Wp + f * 32);
                mma_bf16(acc[f], ah, bv.x, bv.y);
                mma_bf16(acc[f], al, bv.x, bv.y);
                mma_bf16(acc[f], ah, bv.z, bv.w);
            }
        }
        if (pf) stage_x(bufn, sr, sq, xv0, xv1);
        __syncthreads();
    }

    // epilogue: acc -> sU (rows < 88 only)
    {
        int rg = rb + g;
#pragma unroll
        for (int f = 0; f < 8; f++) {
            int cb = wn * 64 + f * 8 + 2 * q;
            if (rg < TM)
                *reinterpret_cast<float2*>(&sU[rg * USTRIDE + cb]) =
                    make_float2(acc[f][0], acc[f][1]);
            if (rg + 8 < TM)
                *reinterpret_cast<float2*>(&sU[(rg + 8) * USTRIDE + cb]) =
                    make_float2(acc[f][2], acc[f][3]);
        }
    }
    __syncthreads();

    // ---- mix1 on tensor pipe: H = relu(A@U + b0) -> sH ----
    mix_mma<false>(wid, g, q, l, sU, sAs, sH, sP, b0);
    if (wid < 4) mix_mma<false>(12 + wid, g, q, l, sU, sAs, sH, sP, b0);
    __syncthreads();

    // ---- phase 3: V = H @ W1^T (K=128); no internal barriers ----
#pragma unroll
    for (int f = 0; f < 8; f++)
#pragma unroll
        for (int i = 0; i < 4; i++) acc[f][i] = 0.f;

    constexpr int NC2 = HN / 32;   // 4
#pragma unroll 1
    for (int kc = 0; kc < NC2; kc++) {
#pragma unroll
        for (int sp = 0; sp < 2; sp++) {
            int p0 = kc * 16 + sp * 8 + q;
            uint2 u00 = sH[(rb + g) * HSTRIDE + p0];
            uint2 u10 = sH[(rb + 8 + g) * HSTRIDE + p0];
            uint2 u01 = sH[(rb + g) * HSTRIDE + p0 + 4];
            uint2 u11 = sH[(rb + 8 + g) * HSTRIDE + p0 + 4];
            uint32_t ah[4] = { u00.x, u10.x, u01.x, u11.x };
            uint32_t al[4] = { u00.y, u10.y, u01.y, u11.y };
            const uint4* Wp = W1s + (size_t)(kc * 2 + sp) * 512 + wn * 256 + l;
#pragma unroll
            for (int f = 0; f < 8; f++) {
                uint4 bv = __ldg(Wp + f * 32);
                mma_bf16(acc[f], ah, bv.x, bv.y);
                mma_bf16(acc[f], al, bv.x, bv.y);
                mma_bf16(acc[f], ah, bv.z, bv.w);
            }
        }
    }

    // epilogue: acc -> sU (disjoint from sH reads; barrier after)
    {
        int rg = rb + g;
#pragma unroll
        for (int f = 0; f < 8; f++) {
            int cb = wn * 64 + f * 8 + 2 * q;
            if (rg < TM)
                *reinterpret_cast<float2*>(&sU[rg * USTRIDE + cb]) =
                    make_float2(acc[f][0], acc[f][1]);
            if (rg + 8 < TM)
                *reinterpret_cast<float2*>(&sU[(rg + 8) * USTRIDE + cb]) =
                    make_float2(acc[f][2], acc[f][3]);
        }
    }
    __syncthreads();

    // ---- mix2 on tensor pipe: partial column sums -> sP ----
    mix_mma<true>(wid, g, q, l, sU, sAs, sH, sP, b1);
    if (wid < 4) mix_mma<true>(12 + wid, g, q, l, sU, sAs, sH, sP, b1);
    __syncthreads();

    // ---- final combine: mean over c -> out ----
    for (int i = t; i < G * HN; i += NTH) {
        int gg = i >> 7, h = i & 127;
        float s = sP[(gg * 2) * HN + h] + sP[(gg * 2 + 1) * HN + h];
        out[(size_t)(bt0 + gg) * HN + h] = s * (1.0f / 22.0f);
    }
}

// ---------------- launch ----------------
extern "C" void kernel_launch(void* const* d_in, const int* in_sizes, int n_in,
                              void* d_out, int out_size) {
    const float* x  = (const float*)d_in[0];
    const float* A  = (const float*)d_in[1];
    const float* W0 = (const float*)d_in[2];
    const float* b0 = (const float*)d_in[3];
    const float* W1 = (const float*)d_in[4];
    const float* b1 = (const float*)d_in[5];
    float* out = (float*)d_out;

    const int BT = in_sizes[1] / (CN * CN);      // 16384
    const int grid = (BT * CN) / TM;             // 4096

    void *pW0 = nullptr, *pW1 = nullptr;
    cudaGetSymbolAddress(&pW0, g_W0s);
    cudaGetSymbolAddress(&pW1, g_W1s);
    uint4* W0s = (uint4*)pW0;
    uint4* W1s = (uint4*)pW1;

    cudaFuncSetAttribute(fused_all,
                         cudaFuncAttributeMaxDynamicSharedMemorySize, SMEM_TOTAL);

    const int n0 = (FN / 16) * 512;              // 6144
    const int n1 = (HN / 16) * 512;              // 4096
    prep_w<<<(n0 + 255) / 256, 256>>>(W0, FN, W0s);
    prep_w<<<(n1 + 255) / 256, 256>>>(W1, HN, W1s);

    fused_all<<<grid, NTH, SMEM_TOTAL>>>(x, W0s, W1s, A, b0, b1, out);
}

// round 15
// speedup vs baseline: 2.0054x; 2.0054x over previous
#include <cuda_runtime.h>
#include <cuda_fp16.h>
#include <cstdint>
#include <cstddef>

#define CN 22
#define FN 192
#define HN 128
#define TM 176                  // CTA M-tile = 8 bt-groups
#define NTH 704                 // 22 warps: 11 M x 2 N, warp tile 16x64

// weights pre-split fp16 hi/lo, MMA-fragment order: t = s*512 + f*32 + lane
// uint4 = { bh0, bh1, bl0, bl1 }  (hi pair k0/k0+1, hi pair k0+8/k0+9, los)
__device__ uint4 g_W0s[(FN / 16) * 512];
__device__ uint4 g_W1s[(HN / 16) * 512];

// ---- smem layout (bytes) ----
// Region R [0, 92928): phase1 = two buffers { X 14080 | W 16384 } = 30464 each
//                      phase2/4 = U/V tile float[176][132] = 92928
//                      phase3  = two W1 chunk buffers (16384 each) at offset 0
#define OFF_X   0
#define OFF_W   14080
#define BUFS    30464
#define XSTRIDE 20              // uint32 (fp16 pairs) per row, 16 used + 4 pad
#define USTRIDE 132
// persistent:
#define OFF_H   92928           // uint32 sH[176][68] fp16 pairs = 47872
#define HSTRIDE 68
#define OFF_A   140800          // float[8][22][24] = 16896
#define SMEM_TOTAL 157696

__device__ __forceinline__ uint32_t smem_u32(const void* p) {
    uint32_t a;
    asm("{ .reg .u64 t; cvta.to.shared.u64 t, %1; cvt.u32.u64 %0, t; }" : "=r"(a) : "l"(p));
    return a;
}
#define CP_ASYNC16(dst_u32, src_gptr) \
    asm volatile("cp.async.cg.shared.global [%0], [%1], 16;" \
                 :: "r"(dst_u32), "l"(src_gptr) : "memory")
#define CP_COMMIT() asm volatile("cp.async.commit_group;" ::: "memory")
#define CP_WAIT0()  asm volatile("cp.async.wait_group 0;" ::: "memory")

__device__ __forceinline__ uint32_t pack_f16(float x, float y) {
    __half2 h = __floats2half2_rn(x, y);
    return *reinterpret_cast<uint32_t*>(&h);
}
__device__ __forceinline__ uint32_t pack_f16_resid(float x, float y, uint32_t hi) {
    __half2 h = *reinterpret_cast<__half2*>(&hi);
    return pack_f16(x - __half2float(h.x), y - __half2float(h.y));
}

// ---- weight prep (both layers, one launch): fp32 -> fragment-order fp16 hi/lo ----
__global__ void prep_w_all(const float* __restrict__ W0, const float* __restrict__ W1,
                           uint4* __restrict__ o0, uint4* __restrict__ o1) {
    int t = blockIdx.x * blockDim.x + threadIdx.x;
    const int n0 = (FN / 16) * 512, n1 = (HN / 16) * 512;
    const float* W;
    uint4* out;
    int K;
    if (t < n0) { W = W0; out = o0; K = FN; }
    else if (t < n0 + n1) { t -= n0; W = W1; out = o1; K = HN; }
    else return;
    int l = t & 31;
    int f = (t >> 5) & 15;
    int s = t >> 9;
    int n = f * 8 + (l >> 2);
    int k0 = s * 16 + (l & 3) * 2;
    const float* wr = W + (size_t)n * K;
    float w00 = wr[k0], w01 = wr[k0 + 1], w10 = wr[k0 + 8], w11 = wr[k0 + 9];
    uint32_t h0 = pack_f16(w00, w01), h1 = pack_f16(w10, w11);
    uint32_t l0 = pack_f16_resid(w00, w01, h0), l1 = pack_f16_resid(w10, w11, h1);
    out[t] = make_uint4(h0, h1, l0, l1);
}

// ---- mma.sync m16n8k16 row.col fp16 -> f32 ----
__device__ __forceinline__ void mma_f16(float* c, const uint32_t* a, uint32_t b0, uint32_t b1) {
    asm volatile(
        "mma.sync.aligned.m16n8k16.row.col.f32.f16.f16.f32 "
        "{%0,%1,%2,%3}, {%4,%5,%6,%7}, {%8,%9}, {%0,%1,%2,%3};"
        : "+f"(c[0]), "+f"(c[1]), "+f"(c[2]), "+f"(c[3])
        : "r"(a[0]), "r"(a[1]), "r"(a[2]), "r"(a[3]), "r"(b0), "r"(b1));
}

// stage 8 fp32 (one thread's k-quarter) as 4 fp16 pairs, one STS.128
__device__ __forceinline__ void stage_x(char* buf, int sr, int sq, float4 a, float4 b) {
    uint32_t* sX = reinterpret_cast<uint32_t*>(buf + OFF_X);
    uint32_t p0 = pack_f16(a.x, a.y), p1 = pack_f16(a.z, a.w);
    uint32_t p2 = pack_f16(b.x, b.y), p3 = pack_f16(b.z, b.w);
    *reinterpret_cast<uint4*>(&sX[sr * XSTRIDE + sq * 4]) = make_uint4(p0, p1, p2, p3);
}

// ---- whole network, one kernel ----
__global__ void __launch_bounds__(NTH, 1) fused_all(
    const float* __restrict__ x,
    const uint4* __restrict__ W0s, const uint4* __restrict__ W1s,
    const float* __restrict__ A,
    const float* __restrict__ b0, const float* __restrict__ b1,
    float* __restrict__ out)
{
    extern __shared__ __align__(16) char sm[];
    const int t = threadIdx.x;
    const int wid = t >> 5, l = t & 31;
    const int g = l >> 2, q = l & 3;
    const int wm = wid >> 1, wn = wid & 1;
    const int rb = wm * 16;
    const int row0 = blockIdx.x * TM;
    const int bt0 = blockIdx.x * 8;
    const uint32_t smbase = smem_u32(sm);

    float*    sU = reinterpret_cast<float*>(sm);
    uint32_t* sH = reinterpret_cast<uint32_t*>(sm + OFF_H);
    float*    sA = reinterpret_cast<float*>(sm + OFF_A);

    // ---- load A (persistent, fp32) ----
    {
        const float* Ag = A + (size_t)bt0 * (CN * CN);
        for (int i = t; i < 8 * CN * CN; i += NTH) {
            int gg = i / (CN * CN);
            int rem = i - gg * (CN * CN);
            int c = rem / CN;
            int j = rem - c * CN;
            sA[gg * 528 + c * 24 + j] = Ag[i];
        }
        for (int p = t; p < 8 * CN; p += NTH) {
            sA[p * 24 + 22] = 0.f;
            sA[p * 24 + 23] = 0.f;
        }
    }

    float acc[8][4];
#pragma unroll
    for (int f = 0; f < 8; f++)
#pragma unroll
        for (int i = 0; i < 4; i++) acc[f][i] = 0.f;

    // ================= phase 1: U = x @ W0^T (K=192) =================
    const int sr = t >> 2, sq = t & 3;
    const float* xrow = x + (size_t)(row0 + sr) * FN + sq * 8;
    const char* W0g = reinterpret_cast<const char*>(W0s);

    if (t < 512) {
        CP_ASYNC16(smbase + OFF_W + t * 16, W0g + t * 16);
        CP_ASYNC16(smbase + OFF_W + (t + 512) * 16, W0g + (t + 512) * 16);
    }
    CP_COMMIT();
    {
        float4 a0 = *reinterpret_cast<const float4*>(xrow);
        float4 a1 = *reinterpret_cast<const float4*>(xrow + 4);
        stage_x(sm, sr, sq, a0, a1);
    }
    CP_WAIT0();
    __syncthreads();

    constexpr int NC1 = FN / 32;   // 6
#pragma unroll 1
    for (int kc = 0; kc < NC1; kc++) {
        const int b = kc & 1;
        char* bufc = sm + b * BUFS;
        char* bufn = sm + (b ^ 1) * BUFS;

        float4 xv0, xv1;
        if (kc + 1 < NC1) {
            if (t < 512) {
                uint32_t wdst = smbase + (uint32_t)((b ^ 1) * BUFS + OFF_W);
                const char* wsrc = W0g + (size_t)(kc + 1) * 16384;
                CP_ASYNC16(wdst + t * 16, wsrc + t * 16);
                CP_ASYNC16(wdst + (t + 512) * 16, wsrc + (t + 512) * 16);
            }
            CP_COMMIT();
            xv0 = *reinterpret_cast<const float4*>(xrow + (kc + 1) * 32);
            xv1 = *reinterpret_cast<const float4*>(xrow + (kc + 1) * 32 + 4);
        }

        const uint32_t* sX = reinterpret_cast<const uint32_t*>(bufc + OFF_X);
        const uint4*    sW = reinterpret_cast<const uint4*>(bufc + OFF_W);
#pragma unroll
        for (int sp = 0; sp < 2; sp++) {
            int ab = (rb + g) * XSTRIDE + sp * 8 + q;
            uint32_t av[4] = { sX[ab], sX[ab + 8 * XSTRIDE],
                               sX[ab + 4], sX[ab + 8 * XSTRIDE + 4] };
#pragma unroll
            for (int f = 0; f < 8; f++) {
                uint4 bv = sW[(sp * 16 + wn * 8 + f) * 32 + l];
                mma_f16(acc[f], av, bv.x, bv.y);   // A * Whi
                mma_f16(acc[f], av, bv.z, bv.w);   // A * Wlo
            }
        }

        if (kc + 1 < NC1) stage_x(bufn, sr, sq, xv0, xv1);
        CP_WAIT0();
        __syncthreads();
    }

    // ================= phase 2: acc -> sU; mix1 (fp32) -> sH fp16 =================
    {
        int rg = rb + g;
#pragma unroll
        for (int f = 0; f < 8; f++) {
            int cb = wn * 64 + f * 8 + 2 * q;
            *reinterpret_cast<float2*>(&sU[rg * USTRIDE + cb]) =
                make_float2(acc[f][0], acc[f][1]);
            *reinterpret_cast<float2*>(&sU[(rg + 8) * USTRIDE + cb]) =
                make_float2(acc[f][2], acc[f][3]);
        }
    }
    __syncthreads();

    if (t < 512) {   // unit = (group gg, h-pair p)
        int gg = t >> 6, p = t & 63;
        float2 bp = *reinterpret_cast<const float2*>(b0 + 2 * p);
        float2 uu[24];
#pragma unroll
        for (int j = 0; j < CN; j++)
            uu[j] = *reinterpret_cast<const float2*>(&sU[(gg * CN + j) * USTRIDE + 2 * p]);
        uu[22] = make_float2(0.f, 0.f);
        uu[23] = make_float2(0.f, 0.f);
#pragma unroll
        for (int c = 0; c < CN; c++) {
            const float4* ar = reinterpret_cast<const float4*>(&sA[gg * 528 + c * 24]);
            float s0 = 0.f, s1 = 0.f;
#pragma unroll
            for (int jq = 0; jq < 6; jq++) {
                float4 a4 = ar[jq];
                s0 = fmaf(a4.x, uu[jq * 4 + 0].x, s0);
                s1 = fmaf(a4.x, uu[jq * 4 + 0].y, s1);
                s0 = fmaf(a4.y, uu[jq * 4 + 1].x, s0);
                s1 = fmaf(a4.y, uu[jq * 4 + 1].y, s1);
                s0 = fmaf(a4.z, uu[jq * 4 + 2].x, s0);
                s1 = fmaf(a4.z, uu[jq * 4 + 2].y, s1);
                s0 = fmaf(a4.w, uu[jq * 4 + 3].x, s0);
                s1 = fmaf(a4.w, uu[jq * 4 + 3].y, s1);
            }
            float v0 = fmaxf(s0 + bp.x, 0.f);
            float v1 = fmaxf(s1 + bp.y, 0.f);
            sH[(gg * CN + c) * HSTRIDE + p] = pack_f16(v0, v1);
        }
    }
    __syncthreads();

    // ================= phase 3: V = H @ W1^T (K=128) =================
#pragma unroll
    for (int f = 0; f < 8; f++)
#pragma unroll
        for (int i = 0; i < 4; i++) acc[f][i] = 0.f;

    const char* W1g = reinterpret_cast<const char*>(W1s);
    if (t < 512) {
        CP_ASYNC16(smbase + t * 16, W1g + t * 16);
        CP_ASYNC16(smbase + (t + 512) * 16, W1g + (t + 512) * 16);
    }
    CP_COMMIT();
    CP_WAIT0();
    __syncthreads();

    constexpr int NC2 = HN / 32;   // 4
#pragma unroll 1
    for (int kc = 0; kc < NC2; kc++) {
        const int b = kc & 1;
        if (kc + 1 < NC2) {
            if (t < 512) {
                uint32_t wdst = smbase + (uint32_t)((b ^ 1) * 16384);
                const char* wsrc = W1g + (size_t)(kc + 1) * 16384;
                CP_ASYNC16(wdst + t * 16, wsrc + t * 16);
                CP_ASYNC16(wdst + (t + 512) * 16, wsrc + (t + 512) * 16);
            }
            CP_COMMIT();
        }
        const uint4* sW = reinterpret_cast<const uint4*>(sm + b * 16384);
#pragma unroll
        for (int sp = 0; sp < 2; sp++) {
            int ab = (rb + g) * HSTRIDE + kc * 16 + sp * 8 + q;
            uint32_t av[4] = { sH[ab], sH[ab + 8 * HSTRIDE],
                               sH[ab + 4], sH[ab + 8 * HSTRIDE + 4] };
#pragma unroll
            for (int f = 0; f < 8; f++) {
                uint4 bv = sW[(sp * 16 + wn * 8 + f) * 32 + l];
                mma_f16(acc[f], av, bv.x, bv.y);
                mma_f16(acc[f], av, bv.z, bv.w);
            }
        }
        CP_WAIT0();
        __syncthreads();
    }

    // ================= phase 4: acc -> sU; mix2 + mean -> out =================
    {
        int rg = rb + g;
#pragma unroll
        for (int f = 0; f < 8; f++) {
            int cb = wn * 64 + f * 8 + 2 * q;
            *reinterpret_cast<float2*>(&sU[rg * USTRIDE + cb]) =
                make_float2(acc[f][0], acc[f][1]);
            *reinterpret_cast<float2*>(&sU[(rg + 8) * USTRIDE + cb]) =
                make_float2(acc[f][2], acc[f][3]);
        }
    }
    __syncthreads();

    for (int u = t; u < 1024; u += NTH) {
        int gg = u >> 7, h = u & 127;
        float uu[24];
#pragma unroll
        for (int j = 0; j < CN; j++) uu[j] = sU[(gg * CN + j) * USTRIDE + h];
        uu[22] = 0.f; uu[23] = 0.f;
        float bh = __ldg(b1 + h);
        float tot = 0.f;
#pragma unroll
        for (int c = 0; c < CN; c++) {
            const float4* ar = reinterpret_cast<const float4*>(&sA[gg * 528 + c * 24]);
            float s = 0.f;
#pragma unroll
            for (int jq = 0; jq < 6; jq++) {
                float4 a4 = ar[jq];
                s = fmaf(a4.x, uu[jq * 4 + 0], s);
                s = fmaf(a4.y, uu[jq * 4 + 1], s);
                s = fmaf(a4.z, uu[jq * 4 + 2], s);
                s = fmaf(a4.w, uu[jq * 4 + 3], s);
            }
            tot += fmaxf(s + bh, 0.f);
        }
        out[(size_t)(bt0 + gg) * HN + h] = tot * (1.0f / 22.0f);
    }
}

// ---------------- launch ----------------
extern "C" void kernel_launch(void* const* d_in, const int* in_sizes, int n_in,
                              void* d_out, int out_size) {
    const float* x  = (const float*)d_in[0];
    const float* A  = (const float*)d_in[1];
    const float* W0 = (const float*)d_in[2];
    const float* b0 = (const float*)d_in[3];
    const float* W1 = (const float*)d_in[4];
    const float* b1 = (const float*)d_in[5];
    float* out = (float*)d_out;

    const int BT = in_sizes[1] / (CN * CN);      // 16384
    const int grid = (BT * CN) / TM;             // 2048

    void *pW0 = nullptr, *pW1 = nullptr;
    cudaGetSymbolAddress(&pW0, g_W0s);
    cudaGetSymbolAddress(&pW1, g_W1s);
    uint4* W0s = (uint4*)pW0;
    uint4* W1s = (uint4*)pW1;

    cudaFuncSetAttribute(fused_all,
                         cudaFuncAttributeMaxDynamicSharedMemorySize, SMEM_TOTAL);

    const int ntot = (FN / 16) * 512 + (HN / 16) * 512;   // 10240
    prep_w_all<<<(ntot + 255) / 256, 256>>>(W0, W1, W0s, W1s);

    fused_all<<<grid, NTH, SMEM_TOTAL>>>(x, W0s, W1s, A, b0, b1, out);
}